// round 5
// baseline (speedup 1.0000x reference)
#include <cuda_runtime.h>
#include <cuda_fp16.h>
#include <math.h>

#define BB 2
#define CC 64
#define NPTS 4096
#define MM 256
#define NS 32
#define R2 0.04f

// -------- scratch (device globals; no allocation allowed) --------
// zeroed region packed in ONE struct -> ONE memset node
struct ZScratch {
    float  G[BB*CC*CC];
    float  sv[BB*CC];
    double stat[48];      // s1[8],ss1[8],s2[8],ss2[8],s3[8],ss3[8]
    int    bar;
    int    cnt[BB*NPTS];
};
__device__ ZScratch g_z;

__device__ int     g_idx[BB*NPTS*NS];
__device__ __half2 g_featsh[BB*NPTS*(MM/2)];  // (B, N, M/2) fp16 pairs
__device__ __half2 g_h2[BB*NPTS*(MM/2)];      // (B, N, M/2) fp16 pairs
__device__ float   g_oraw[BB*CC*NPTS];        // (B, C, N)

#define G_S1  (g_z.stat)
#define G_SS1 (g_z.stat + 8)
#define G_S2  (g_z.stat + 16)
#define G_SS2 (g_z.stat + 24)
#define G_S3  (g_z.stat + 32)
#define G_SS3 (g_z.stat + 40)

__device__ __forceinline__ float gelu_f(float v) {
    return 0.5f * v * (1.0f + erff(v * 0.70710678118654752f));
}

// -------- K1: ball query (one warp per query point) + counts --------
__global__ void k_ball(const float* __restrict__ pos) {
    extern __shared__ float sm[];
    float* sx = sm;
    float* sy = sm + NPTS;
    float* sz = sm + 2*NPTS;
    int*   widx = (int*)(sm + 3*NPTS);   // 32 warps * 32 entries

    int tid = threadIdx.x;
    int b = blockIdx.x / (NPTS/32);
    int nbase = (blockIdx.x % (NPTS/32)) * 32;
    const float* pb = pos + b * 3 * NPTS;
    for (int i = tid; i < NPTS; i += 1024) {
        sx[i] = pb[i];
        sy[i] = pb[NPTS + i];
        sz[i] = pb[2*NPTS + i];
    }
    __syncthreads();

    int warp = tid >> 5, lane = tid & 31;
    int n = nbase + warp;
    float xn = sx[n], yn = sy[n], zn = sz[n];
    float sqn = xn*xn + yn*yn + zn*zn;
    int cnt = 0, firstm = -1;
    int* wl = widx + warp * NS;

    for (int base = 0; base < NPTS && cnt < NS; base += 32) {
        int mq = base + lane;
        float xm = sx[mq], ym = sy[mq], zm = sz[mq];
        float sqm = xm*xm + ym*ym + zm*zm;
        float dot = xn*xm + yn*ym + zn*zm;
        float d = sqn + sqm - 2.0f * dot;
        bool q = !(d > R2);
        unsigned mask = __ballot_sync(0xffffffffu, q);
        if (mask) {
            if (firstm < 0) firstm = base + __ffs(mask) - 1;
            int nq = __popc(mask);
            int slots = NS - cnt;
            if (q) {
                int rank = __popc(mask & ((1u << lane) - 1u));
                if (rank < slots) wl[cnt + rank] = mq;
            }
            cnt += (nq < slots) ? nq : slots;
        }
    }
    __syncwarp();
    if (lane >= cnt) wl[lane] = firstm;
    __syncwarp();
    int j = wl[lane];
    g_idx[(b*NPTS + n)*NS + lane] = j;
    atomicAdd(&g_z.cnt[b*NPTS + j], 1);
}

// -------- K2: Gram + GN1 stats, fused with device barrier --------
// grid 128 (all resident), block 256. Blocks 0-7 finish stats after barrier.
__global__ void k_gramstats(const float* __restrict__ x, const float* __restrict__ w1,
                            const float* __restrict__ b1) {
    __shared__ float sA[64*68];           // phase1: x tile [c][n] pitch 68 ; phase2: sG
    __shared__ float sB[64*65];           // phase2: sw [m][c] pitch 65
    __shared__ float ssv[CC];
    __shared__ double sd[64], ssd[64];
    int tid = threadIdx.x;
    int blk = blockIdx.x;
    int b = blk >> 6, n0 = (blk & 63) * 64;

    // ---- phase 1: Gram partial ----
    for (int e = tid; e < 4096; e += 256) {
        int c = e >> 6, nn = e & 63;
        sA[c*68 + nn] = x[(b*CC + c)*NPTS + n0 + nn];
    }
    __syncthreads();

    int tx = tid & 15, ty = tid >> 4;
    float acc[4][4] = {};
#pragma unroll 16
    for (int k = 0; k < 64; k++) {
        float a[4], h[4];
#pragma unroll
        for (int i = 0; i < 4; i++) a[i] = sA[(ty*4 + i)*68 + k];
#pragma unroll
        for (int j = 0; j < 4; j++) h[j] = sA[(tx*4 + j)*68 + k];
#pragma unroll
        for (int i = 0; i < 4; i++)
#pragma unroll
            for (int j = 0; j < 4; j++)
                acc[i][j] = fmaf(a[i], h[j], acc[i][j]);
    }
    float* Gb = g_z.G + b*CC*CC;
#pragma unroll
    for (int i = 0; i < 4; i++)
#pragma unroll
        for (int j = 0; j < 4; j++)
            atomicAdd(&Gb[(ty*4 + i)*CC + tx*4 + j], acc[i][j]);
    if (tid < CC) {
        float s = 0.f;
#pragma unroll
        for (int nn = 0; nn < 64; nn++) s += sA[tid*68 + nn];
        atomicAdd(&g_z.sv[b*CC + tid], s);
    }

    // ---- barrier ----
    __syncthreads();
    __threadfence();
    if (tid == 0) atomicAdd(&g_z.bar, 1);
    if (blk >= 8) return;

    if (tid == 0) {
        while (atomicAdd(&g_z.bar, 0) < 128) {}
    }
    __syncthreads();

    // ---- phase 2: stats for bg = blk ----
    int bg = blk;
    int sb = bg >> 2, m0 = (bg & 3) * 64;
    for (int e = tid; e < CC*CC; e += 256) sA[e] = __ldcg(&g_z.G[sb*CC*CC + e]);
    for (int e = tid; e < 64*CC; e += 256) sB[(e >> 6)*65 + (e & 63)] = w1[(m0 + (e >> 6))*CC + (e & 63)];
    if (tid < CC) ssv[tid] = __ldcg(&g_z.sv[sb*CC + tid]);
    __syncthreads();

    int mi = tid >> 2, part = tid & 3;
    float q = 0.f, l = 0.f;
    const float* wrow = sB + mi*65;
#pragma unroll
    for (int cc = 0; cc < 16; cc++) {
        int c = part*16 + cc;
        float wc = wrow[c];
        float in0 = 0.f, in1 = 0.f;
#pragma unroll
        for (int c2 = 0; c2 < 64; c2 += 2) {
            in0 = fmaf(wrow[c2],   sA[c*CC + c2],   in0);
            in1 = fmaf(wrow[c2+1], sA[c*CC + c2+1], in1);
        }
        q = fmaf(wc, in0 + in1, q);
        l = fmaf(wc, ssv[c], l);
    }
    q += __shfl_down_sync(0xffffffffu, q, 1);
    q += __shfl_down_sync(0xffffffffu, q, 2);
    l += __shfl_down_sync(0xffffffffu, l, 1);
    l += __shfl_down_sync(0xffffffffu, l, 2);
    if (part == 0) {
        double bb = (double)b1[m0 + mi];
        sd[mi]  = (double)l + 4096.0 * bb;
        ssd[mi] = (double)q + 2.0 * bb * (double)l + 4096.0 * bb * bb;
    }
    __syncthreads();
    for (int s = 32; s > 0; s >>= 1) {
        if (tid < s) { sd[tid] += sd[tid + s]; ssd[tid] += ssd[tid + s]; }
        __syncthreads();
    }
    if (tid == 0) { G_S1[bg] = sd[0]; G_SS1[bg] = ssd[0]; }
}

// -------- K3: GEMM1 (64m x 64n, 4x4 thread) + GN1 + GELU + fp16 feats
//          + count-weighted GN2 stats --------
__global__ void k_gemm1f(const float* __restrict__ x, const float* __restrict__ w1,
                         const float* __restrict__ b1, const float* __restrict__ g1,
                         const float* __restrict__ be1, const float* __restrict__ wd) {
    __shared__ float sWt[64*68];      // [k][m]
    __shared__ float sX[64*64];       // [k][n]
    __shared__ float red1[256], red2[256];
    int b = blockIdx.z, m0 = blockIdx.y * 64, n0 = blockIdx.x * 64;
    int tid = threadIdx.x;
    int bg = b*4 + blockIdx.y;

    for (int e = tid; e < 4096; e += 256) {
        int m = e >> 6, c = e & 63;
        sWt[c*68 + m] = w1[(m0 + m)*CC + c];
    }
    for (int e = tid; e < 4096; e += 256) {
        int c = e >> 6, nn = e & 63;
        sX[c*64 + nn] = x[(b*CC + c)*NPTS + n0 + nn];
    }
    __syncthreads();

    int tx = tid & 15, ty = tid >> 4;
    float acc[4][4] = {};
#pragma unroll 8
    for (int k = 0; k < 64; k++) {
        float4 a4 = *(float4*)&sWt[k*68 + ty*4];
        float4 h4 = *(float4*)&sX[k*64 + tx*4];
        float a[4] = {a4.x, a4.y, a4.z, a4.w};
        float h[4] = {h4.x, h4.y, h4.z, h4.w};
#pragma unroll
        for (int i = 0; i < 4; i++)
#pragma unroll
            for (int j = 0; j < 4; j++)
                acc[i][j] = fmaf(a[i], h[j], acc[i][j]);
    }

    double mean = G_S1[bg] * (1.0 / (64.0 * 4096.0));
    double var  = G_SS1[bg] * (1.0 / (64.0 * 4096.0)) - mean * mean;
    float rs = (float)rsqrt(var + 1e-5);
    float mn = (float)mean;

    float w[4];
#pragma unroll
    for (int j = 0; j < 4; j++) w[j] = (float)g_z.cnt[b*NPTS + n0 + tx*4 + j];

    float f[4][4];
    float lsum = 0.f, lss = 0.f;
#pragma unroll
    for (int i = 0; i < 4; i++) {
        int m = m0 + ty*4 + i;
        float bb = b1[m];
        float ga = g1[m] * rs;
        float bofs = be1[m] - (mn - bb) * ga;
        float wdm = wd[m];
#pragma unroll
        for (int j = 0; j < 4; j++) {
            float v = gelu_f(fmaf(acc[i][j], ga, bofs));
            f[i][j] = v;
            float v2 = v * wdm;
            lsum = fmaf(w[j], v2, lsum);
            lss  = fmaf(w[j], v2*v2, lss);
        }
    }

    // fp16 write: per n, 4 consecutive m = 2 half2 = uint2
#pragma unroll
    for (int j = 0; j < 4; j++) {
        __half2 hv[2];
        hv[0] = __floats2half2_rn(f[0][j], f[1][j]);
        hv[1] = __floats2half2_rn(f[2][j], f[3][j]);
        int n = n0 + tx*4 + j;
        __half2* dst = g_featsh + (size_t)(b*NPTS + n)*(MM/2) + (m0 >> 1) + ty*2;
        *(uint2*)dst = *(uint2*)hv;
    }

    red1[tid] = lsum; red2[tid] = lss;
    __syncthreads();
    for (int s = 128; s > 0; s >>= 1) {
        if (tid < s) { red1[tid] += red1[tid + s]; red2[tid] += red2[tid + s]; }
        __syncthreads();
    }
    if (tid == 0) {
        atomicAdd(&G_S2[bg],  (double)red1[0]);
        atomicAdd(&G_SS2[bg], (double)red2[0]);
    }
}

// -------- K4: gather + GN2 + maxpool + GELU -> h2 fp16 --------
// grid 4096 (2 points per block), block 256: thread = (mp 0..127, nh 0..1)
__global__ void k_gather(const float* __restrict__ wd, const float* __restrict__ gd,
                         const float* __restrict__ bed) {
    __shared__ int sI[2*NS];
    int blk = blockIdx.x;
    int b = blk >> 11, n0 = (blk & 2047) * 2;
    int tid = threadIdx.x;
    if (tid < 2*NS) sI[tid] = g_idx[(b*NPTS + n0)*NS + tid];
    __syncthreads();

    int mp = tid & 127, nh = tid >> 7;
    int n = n0 + nh;
    int m0c = mp * 2;
    float A[2], Bc[2];
#pragma unroll
    for (int u = 0; u < 2; u++) {
        int m = m0c + u;
        int bg = b*4 + (m >> 6);
        double mean = G_S2[bg] * (1.0 / 8388608.0);
        double var  = G_SS2[bg] * (1.0 / 8388608.0) - mean * mean;
        float rsv = (float)rsqrt(var + 1e-5);
        A[u]  = wd[m] * rsv * gd[m];
        Bc[u] = bed[m] - (float)((double)rsv * mean) * gd[m];
    }
    const __half2* fb = g_featsh + (size_t)b*NPTS*(MM/2) + mp;
    const int* il = sI + nh*NS;
    __half2 negv = __half2half2(__float2half(-65504.f));
    __half2 posv = __half2half2(__float2half( 65504.f));
    __half2 vmax0 = negv, vmax1 = negv, vmin0 = posv, vmin1 = posv;
#pragma unroll
    for (int s = 0; s < NS; s += 2) {
        __half2 v0 = fb[(size_t)il[s]   * (MM/2)];
        __half2 v1 = fb[(size_t)il[s+1] * (MM/2)];
        vmax0 = __hmax2(vmax0, v0); vmin0 = __hmin2(vmin0, v0);
        vmax1 = __hmax2(vmax1, v1); vmin1 = __hmin2(vmin1, v1);
    }
    float2 fmax2 = __half22float2(__hmax2(vmax0, vmax1));
    float2 fmin2 = __half22float2(__hmin2(vmin0, vmin1));
    float v0 = (A[0] >= 0.f) ? fmax2.x : fmin2.x;
    float v1 = (A[1] >= 0.f) ? fmax2.y : fmin2.y;
    float r0 = gelu_f(fmaf(A[0], v0, Bc[0]));
    float r1 = gelu_f(fmaf(A[1], v1, Bc[1]));
    g_h2[(size_t)(b*NPTS + n)*(MM/2) + mp] = __floats2half2_rn(r0, r1);
}

// -------- K5: GEMM2 (64c x 32n, K=256) + GN3 stats --------
// dyn smem: sW2t [256][68] f32 + sH [256][33] f32
#define G2_SMEM ((256*68 + 256*33)*4)
__global__ void k_gemm2(const float* __restrict__ w2, const float* __restrict__ b2) {
    extern __shared__ float smf[];
    float* sW2t = smf;            // [k][c] pitch 68
    float* sH   = smf + 256*68;   // [k][n] pitch 33
    __shared__ float sacc[4], sss[4];

    int b = blockIdx.y, n0 = blockIdx.x * 32;
    int tid = threadIdx.x;
    if (tid < 4) { sacc[tid] = 0.f; sss[tid] = 0.f; }

    for (int e = tid; e < 64*256; e += 256) {
        int c = e >> 8, k = e & 255;
        sW2t[k*68 + c] = w2[e];
    }
    for (int e = tid; e < 32*128; e += 256) {
        int n = e >> 7, mp = e & 127;
        float2 v = __half22float2(g_h2[(size_t)(b*NPTS + n0 + n)*(MM/2) + mp]);
        sH[(2*mp)*33 + n]     = v.x;
        sH[(2*mp + 1)*33 + n] = v.y;
    }
    __syncthreads();

    int tx = tid & 31, ty = tid >> 5;
    float acc[8] = {};
#pragma unroll 4
    for (int k = 0; k < 256; k++) {
        float4 a0 = *(float4*)&sW2t[k*68 + ty*8];
        float4 a1 = *(float4*)&sW2t[k*68 + ty*8 + 4];
        float hv = sH[k*33 + tx];
        acc[0] = fmaf(a0.x, hv, acc[0]);
        acc[1] = fmaf(a0.y, hv, acc[1]);
        acc[2] = fmaf(a0.z, hv, acc[2]);
        acc[3] = fmaf(a0.w, hv, acc[3]);
        acc[4] = fmaf(a1.x, hv, acc[4]);
        acc[5] = fmaf(a1.y, hv, acc[5]);
        acc[6] = fmaf(a1.z, hv, acc[6]);
        acc[7] = fmaf(a1.w, hv, acc[7]);
    }

    float lsum = 0.f, lss = 0.f;
#pragma unroll
    for (int i = 0; i < 8; i++) {
        int c = ty*8 + i;
        float v = acc[i] + b2[c];
        g_oraw[(b*CC + c)*NPTS + n0 + tx] = v;
        lsum += v;
        lss  += v*v;
    }
    int g = ty >> 1;
    atomicAdd(&sacc[g], lsum);
    atomicAdd(&sss[g],  lss);
    __syncthreads();
    if (tid < 4) {
        atomicAdd(&G_S3[b*4 + tid],  (double)sacc[tid]);
        atomicAdd(&G_SS3[b*4 + tid], (double)sss[tid]);
    }
}

// -------- K6: GN3 + residual --------
__global__ void k_final(const float* __restrict__ x, const float* __restrict__ g2,
                        const float* __restrict__ be2, float* __restrict__ out) {
    int i4 = blockIdx.x * 256 + threadIdx.x;
    if (i4 >= BB*CC*NPTS/4) return;
    int i = i4 * 4;
    int b = i >> 18;
    int c = (i >> 12) & 63;
    int bg = b*4 + (c >> 4);
    double mean = G_S3[bg] * (1.0 / 65536.0);
    double var  = G_SS3[bg] * (1.0 / 65536.0) - mean * mean;
    float rs = (float)rsqrt(var + 1e-5);
    float ga = rs * g2[c];
    float bo = be2[c] - (float)mean * ga;
    float4 o = *(const float4*)&g_oraw[i];
    float4 xi = *(const float4*)&x[i];
    o.x = fmaf(o.x, ga, bo) + xi.x;
    o.y = fmaf(o.y, ga, bo) + xi.y;
    o.z = fmaf(o.z, ga, bo) + xi.z;
    o.w = fmaf(o.w, ga, bo) + xi.w;
    *(float4*)&out[i] = o;
}

extern "C" void kernel_launch(void* const* d_in, const int* in_sizes, int n_in,
                              void* d_out, int out_size) {
    const float* x   = (const float*)d_in[0];
    const float* pos = (const float*)d_in[1];
    const float* w1  = (const float*)d_in[2];
    const float* b1  = (const float*)d_in[3];
    const float* g1  = (const float*)d_in[4];
    const float* be1 = (const float*)d_in[5];
    const float* wd  = (const float*)d_in[6];
    const float* gd  = (const float*)d_in[7];
    const float* bed = (const float*)d_in[8];
    const float* w2  = (const float*)d_in[9];
    const float* b2  = (const float*)d_in[10];
    const float* g2  = (const float*)d_in[11];
    const float* be2 = (const float*)d_in[12];
    float* out = (float*)d_out;

    static int inited = 0;
    if (!inited) {
        cudaFuncSetAttribute(k_ball,  cudaFuncAttributeMaxDynamicSharedMemorySize, 3*NPTS*4 + 32*NS*4);
        cudaFuncSetAttribute(k_gemm2, cudaFuncAttributeMaxDynamicSharedMemorySize, G2_SMEM);
        inited = 1;
    }

    void* p_z;
    cudaGetSymbolAddress(&p_z, g_z);
    cudaMemsetAsync(p_z, 0, sizeof(ZScratch));

    k_ball     <<<BB*NPTS/32, 1024, 3*NPTS*4 + 32*NS*4>>>(pos);
    k_gramstats<<<128, 256>>>(x, w1, b1);
    k_gemm1f   <<<dim3(NPTS/64, MM/64, BB), 256>>>(x, w1, b1, g1, be1, wd);
    k_gather   <<<BB*NPTS/2, 256>>>(wd, gd, bed);
    k_gemm2    <<<dim3(NPTS/32, BB), 256, G2_SMEM>>>(w2, b2);
    k_final    <<<(BB*CC*NPTS/4 + 255)/256, 256>>>(x, g2, be2, out);
}

// round 6
// speedup vs baseline: 1.3366x; 1.3366x over previous
#include <cuda_runtime.h>
#include <cuda_fp16.h>
#include <math.h>

#define BB 2
#define CC 64
#define NPTS 4096
#define MM 256
#define NS 32
#define R2 0.04f

// -------- scratch (device globals; no allocation allowed) --------
struct ZScratch {
    float  G[BB*CC*CC];
    float  sv[BB*CC];
    double stat[48];      // s1[8],ss1[8],s2[8],ss2[8],s3[8],ss3[8]
    int    bar;
    int    bar2;
    int    cnt[BB*NPTS];
};
__device__ ZScratch g_z;

__device__ int     g_idx[BB*NPTS*NS];
__device__ __half2 g_featsh[BB*NPTS*(MM/2)];  // (B, N, M/2) fp16 pairs
__device__ __half2 g_h2[BB*NPTS*(MM/2)];      // (B, N, M/2) fp16 pairs

#define G_S1  (g_z.stat)
#define G_SS1 (g_z.stat + 8)
#define G_S2  (g_z.stat + 16)
#define G_SS2 (g_z.stat + 24)
#define G_S3  (g_z.stat + 32)
#define G_SS3 (g_z.stat + 40)

__device__ __forceinline__ float gelu_f(float v) {
    return 0.5f * v * (1.0f + erff(v * 0.70710678118654752f));
}

// -------- K1: ball query (one warp per query point) + counts --------
__global__ void k_ball(const float* __restrict__ pos) {
    extern __shared__ float sm[];
    float* sx = sm;
    float* sy = sm + NPTS;
    float* sz = sm + 2*NPTS;
    int*   widx = (int*)(sm + 3*NPTS);

    int tid = threadIdx.x;
    int b = blockIdx.x / (NPTS/32);
    int nbase = (blockIdx.x % (NPTS/32)) * 32;
    const float* pb = pos + b * 3 * NPTS;
    for (int i = tid; i < NPTS; i += 1024) {
        sx[i] = pb[i];
        sy[i] = pb[NPTS + i];
        sz[i] = pb[2*NPTS + i];
    }
    __syncthreads();

    int warp = tid >> 5, lane = tid & 31;
    int n = nbase + warp;
    float xn = sx[n], yn = sy[n], zn = sz[n];
    float sqn = xn*xn + yn*yn + zn*zn;
    int cnt = 0, firstm = -1;
    int* wl = widx + warp * NS;

    for (int base = 0; base < NPTS && cnt < NS; base += 32) {
        int mq = base + lane;
        float xm = sx[mq], ym = sy[mq], zm = sz[mq];
        float sqm = xm*xm + ym*ym + zm*zm;
        float dot = xn*xm + yn*ym + zn*zm;
        float d = sqn + sqm - 2.0f * dot;
        bool q = !(d > R2);
        unsigned mask = __ballot_sync(0xffffffffu, q);
        if (mask) {
            if (firstm < 0) firstm = base + __ffs(mask) - 1;
            int nq = __popc(mask);
            int slots = NS - cnt;
            if (q) {
                int rank = __popc(mask & ((1u << lane) - 1u));
                if (rank < slots) wl[cnt + rank] = mq;
            }
            cnt += (nq < slots) ? nq : slots;
        }
    }
    __syncwarp();
    if (lane >= cnt) wl[lane] = firstm;
    __syncwarp();
    int j = wl[lane];
    g_idx[(b*NPTS + n)*NS + lane] = j;
    atomicAdd(&g_z.cnt[b*NPTS + j], 1);
}

// -------- K2: Gram + GN1 stats (fused, device barrier; grid 128 all-resident) --------
__global__ void k_gramstats(const float* __restrict__ x, const float* __restrict__ w1,
                            const float* __restrict__ b1) {
    __shared__ float sA[64*68];
    __shared__ float sB[64*65];
    __shared__ float ssv[CC];
    __shared__ double sd[64], ssd[64];
    int tid = threadIdx.x;
    int blk = blockIdx.x;
    int b = blk >> 6, n0 = (blk & 63) * 64;

    for (int e = tid; e < 4096; e += 256) {
        int c = e >> 6, nn = e & 63;
        sA[c*68 + nn] = x[(b*CC + c)*NPTS + n0 + nn];
    }
    __syncthreads();

    int tx = tid & 15, ty = tid >> 4;
    float acc[4][4] = {};
#pragma unroll 16
    for (int k = 0; k < 64; k++) {
        float a[4], h[4];
#pragma unroll
        for (int i = 0; i < 4; i++) a[i] = sA[(ty*4 + i)*68 + k];
#pragma unroll
        for (int j = 0; j < 4; j++) h[j] = sA[(tx*4 + j)*68 + k];
#pragma unroll
        for (int i = 0; i < 4; i++)
#pragma unroll
            for (int j = 0; j < 4; j++)
                acc[i][j] = fmaf(a[i], h[j], acc[i][j]);
    }
    float* Gb = g_z.G + b*CC*CC;
#pragma unroll
    for (int i = 0; i < 4; i++)
#pragma unroll
        for (int j = 0; j < 4; j++)
            atomicAdd(&Gb[(ty*4 + i)*CC + tx*4 + j], acc[i][j]);
    if (tid < CC) {
        float s = 0.f;
#pragma unroll
        for (int nn = 0; nn < 64; nn++) s += sA[tid*68 + nn];
        atomicAdd(&g_z.sv[b*CC + tid], s);
    }

    __syncthreads();
    __threadfence();
    if (tid == 0) atomicAdd(&g_z.bar, 1);
    if (blk >= 8) return;

    if (tid == 0) {
        while (atomicAdd(&g_z.bar, 0) < 128) {}
    }
    __syncthreads();

    int bg = blk;
    int sb = bg >> 2, m0 = (bg & 3) * 64;
    for (int e = tid; e < CC*CC; e += 256) sA[e] = __ldcg(&g_z.G[sb*CC*CC + e]);
    for (int e = tid; e < 64*CC; e += 256) sB[(e >> 6)*65 + (e & 63)] = w1[(m0 + (e >> 6))*CC + (e & 63)];
    if (tid < CC) ssv[tid] = __ldcg(&g_z.sv[sb*CC + tid]);
    __syncthreads();

    int mi = tid >> 2, part = tid & 3;
    float q = 0.f, l = 0.f;
    const float* wrow = sB + mi*65;
#pragma unroll
    for (int cc = 0; cc < 16; cc++) {
        int c = part*16 + cc;
        float wc = wrow[c];
        float in0 = 0.f, in1 = 0.f;
#pragma unroll
        for (int c2 = 0; c2 < 64; c2 += 2) {
            in0 = fmaf(wrow[c2],   sA[c*CC + c2],   in0);
            in1 = fmaf(wrow[c2+1], sA[c*CC + c2+1], in1);
        }
        q = fmaf(wc, in0 + in1, q);
        l = fmaf(wc, ssv[c], l);
    }
    q += __shfl_down_sync(0xffffffffu, q, 1);
    q += __shfl_down_sync(0xffffffffu, q, 2);
    l += __shfl_down_sync(0xffffffffu, l, 1);
    l += __shfl_down_sync(0xffffffffu, l, 2);
    if (part == 0) {
        double bb = (double)b1[m0 + mi];
        sd[mi]  = (double)l + 4096.0 * bb;
        ssd[mi] = (double)q + 2.0 * bb * (double)l + 4096.0 * bb * bb;
    }
    __syncthreads();
    for (int s = 32; s > 0; s >>= 1) {
        if (tid < s) { sd[tid] += sd[tid + s]; ssd[tid] += ssd[tid + s]; }
        __syncthreads();
    }
    if (tid == 0) { G_S1[bg] = sd[0]; G_SS1[bg] = ssd[0]; }
}

// -------- K3: GEMM1 + GN1 + GELU + fp16 feats + count-weighted GN2 stats --------
__global__ void k_gemm1f(const float* __restrict__ x, const float* __restrict__ w1,
                         const float* __restrict__ b1, const float* __restrict__ g1,
                         const float* __restrict__ be1, const float* __restrict__ wd) {
    __shared__ float sWt[64*68];
    __shared__ float sX[64*64];
    __shared__ float red1[256], red2[256];
    int b = blockIdx.z, m0 = blockIdx.y * 64, n0 = blockIdx.x * 64;
    int tid = threadIdx.x;
    int bg = b*4 + blockIdx.y;

    for (int e = tid; e < 4096; e += 256) {
        int m = e >> 6, c = e & 63;
        sWt[c*68 + m] = w1[(m0 + m)*CC + c];
    }
    for (int e = tid; e < 4096; e += 256) {
        int c = e >> 6, nn = e & 63;
        sX[c*64 + nn] = x[(b*CC + c)*NPTS + n0 + nn];
    }
    __syncthreads();

    int tx = tid & 15, ty = tid >> 4;
    float acc[4][4] = {};
#pragma unroll 8
    for (int k = 0; k < 64; k++) {
        float4 a4 = *(float4*)&sWt[k*68 + ty*4];
        float4 h4 = *(float4*)&sX[k*64 + tx*4];
        float a[4] = {a4.x, a4.y, a4.z, a4.w};
        float h[4] = {h4.x, h4.y, h4.z, h4.w};
#pragma unroll
        for (int i = 0; i < 4; i++)
#pragma unroll
            for (int j = 0; j < 4; j++)
                acc[i][j] = fmaf(a[i], h[j], acc[i][j]);
    }

    double mean = G_S1[bg] * (1.0 / (64.0 * 4096.0));
    double var  = G_SS1[bg] * (1.0 / (64.0 * 4096.0)) - mean * mean;
    float rs = (float)rsqrt(var + 1e-5);
    float mn = (float)mean;

    float w[4];
#pragma unroll
    for (int j = 0; j < 4; j++) w[j] = (float)g_z.cnt[b*NPTS + n0 + tx*4 + j];

    float f[4][4];
    float lsum = 0.f, lss = 0.f;
#pragma unroll
    for (int i = 0; i < 4; i++) {
        int m = m0 + ty*4 + i;
        float bb = b1[m];
        float ga = g1[m] * rs;
        float bofs = be1[m] - (mn - bb) * ga;
        float wdm = wd[m];
#pragma unroll
        for (int j = 0; j < 4; j++) {
            float v = gelu_f(fmaf(acc[i][j], ga, bofs));
            f[i][j] = v;
            float v2 = v * wdm;
            lsum = fmaf(w[j], v2, lsum);
            lss  = fmaf(w[j], v2*v2, lss);
        }
    }

#pragma unroll
    for (int j = 0; j < 4; j++) {
        __half2 hv[2];
        hv[0] = __floats2half2_rn(f[0][j], f[1][j]);
        hv[1] = __floats2half2_rn(f[2][j], f[3][j]);
        int n = n0 + tx*4 + j;
        __half2* dst = g_featsh + (size_t)(b*NPTS + n)*(MM/2) + (m0 >> 1) + ty*2;
        *(uint2*)dst = *(uint2*)hv;
    }

    red1[tid] = lsum; red2[tid] = lss;
    __syncthreads();
    for (int s = 128; s > 0; s >>= 1) {
        if (tid < s) { red1[tid] += red1[tid + s]; red2[tid] += red2[tid + s]; }
        __syncthreads();
    }
    if (tid == 0) {
        atomicAdd(&G_S2[bg],  (double)red1[0]);
        atomicAdd(&G_SS2[bg], (double)red2[0]);
    }
}

// -------- K4: gather (warp per point, uint4 loads) + GN2 + maxpool + GELU -> h2 fp16 --------
// grid BB*NPTS/8 = 1024, block 256 (8 warps = 8 points); lane covers 8 channels
__global__ void k_gather(const float* __restrict__ wd, const float* __restrict__ gd,
                         const float* __restrict__ bed) {
    __shared__ float sA[MM], sBc[MM];
    __shared__ int sI[8*NS];
    int blk = blockIdx.x;
    int b = blk >> 9, n0 = (blk & 511) * 8;
    int tid = threadIdx.x;

    // per-channel GN2 affine coeffs (256 channels, one per thread)
    {
        int m = tid;
        int bg = b*4 + (m >> 6);
        double mean = G_S2[bg] * (1.0 / 8388608.0);
        double var  = G_SS2[bg] * (1.0 / 8388608.0) - mean * mean;
        float rsv = (float)rsqrt(var + 1e-5);
        sA[m]  = wd[m] * rsv * gd[m];
        sBc[m] = bed[m] - (float)((double)rsv * mean) * gd[m];
    }
    sI[tid] = g_idx[(b*NPTS + n0)*NS + tid];
    __syncthreads();

    int warp = tid >> 5, lane = tid & 31;
    int n = n0 + warp;
    const int* il = sI + warp * NS;
    const uint4* fb = ((const uint4*)(g_featsh + (size_t)b*NPTS*(MM/2))) + lane;

    __half2 hneg = __half2half2(__float2half(-65504.f));
    __half2 hpos = __half2half2(__float2half( 65504.f));
    __half2 mxA[4] = {hneg, hneg, hneg, hneg};
    __half2 mnA[4] = {hpos, hpos, hpos, hpos};
    __half2 mxB[4] = {hneg, hneg, hneg, hneg};
    __half2 mnB[4] = {hpos, hpos, hpos, hpos};

#pragma unroll
    for (int s = 0; s < NS; s += 2) {
        uint4 va = fb[(size_t)il[s]   * 32];
        uint4 vb = fb[(size_t)il[s+1] * 32];
        const __half2* ha = (const __half2*)&va;
        const __half2* hb = (const __half2*)&vb;
#pragma unroll
        for (int u = 0; u < 4; u++) {
            mxA[u] = __hmax2(mxA[u], ha[u]); mnA[u] = __hmin2(mnA[u], ha[u]);
            mxB[u] = __hmax2(mxB[u], hb[u]); mnB[u] = __hmin2(mnB[u], hb[u]);
        }
    }

    __half2 outv[4];
#pragma unroll
    for (int u = 0; u < 4; u++) {
        float2 fmx = __half22float2(__hmax2(mxA[u], mxB[u]));
        float2 fmn = __half22float2(__hmin2(mnA[u], mnB[u]));
        int ch = 8*lane + 2*u;
        float A0 = sA[ch],   B0 = sBc[ch];
        float A1 = sA[ch+1], B1 = sBc[ch+1];
        float v0 = (A0 >= 0.f) ? fmx.x : fmn.x;
        float v1 = (A1 >= 0.f) ? fmx.y : fmn.y;
        float r0 = gelu_f(fmaf(A0, v0, B0));
        float r1 = gelu_f(fmaf(A1, v1, B1));
        outv[u] = __floats2half2_rn(r0, r1);
    }
    ((uint4*)(g_h2 + (size_t)(b*NPTS + n)*(MM/2)))[lane] = *(uint4*)outv;
}

// -------- K5: GEMM2 (64c x 32n, K chunked by 64) + GN3 stats + barrier + GN3 apply + residual --------
// grid (NPTS/32, BB) = 256 blocks (all resident), block 256
__global__ void k_gemm2f(const float* __restrict__ w2, const float* __restrict__ b2,
                         const float* __restrict__ x, const float* __restrict__ g2,
                         const float* __restrict__ be2, float* __restrict__ out) {
    __shared__ float sW2t[64*68];     // [k][c]
    __shared__ float sH[64*33];       // [k][n]
    __shared__ float sacc[4], sss[4];
    __shared__ float sMean[4], sRs[4];

    int b = blockIdx.y, n0 = blockIdx.x * 32;
    int tid = threadIdx.x;
    if (tid < 4) { sacc[tid] = 0.f; sss[tid] = 0.f; }

    int tx = tid & 31, ty = tid >> 5;
    float acc[8] = {};

    for (int kc = 0; kc < 4; kc++) {
        __syncthreads();
        for (int e = tid; e < 4096; e += 256) {
            int c = e >> 6, k = e & 63;
            sW2t[k*68 + c] = w2[c*MM + kc*64 + k];
        }
        for (int e = tid; e < 1024; e += 256) {
            int n = e >> 5, mp = e & 31;
            float2 v = __half22float2(g_h2[(size_t)(b*NPTS + n0 + n)*(MM/2) + kc*32 + mp]);
            sH[(2*mp)*33 + n]     = v.x;
            sH[(2*mp + 1)*33 + n] = v.y;
        }
        __syncthreads();

#pragma unroll 4
        for (int k = 0; k < 64; k++) {
            float4 a0 = *(float4*)&sW2t[k*68 + ty*8];
            float4 a1 = *(float4*)&sW2t[k*68 + ty*8 + 4];
            float hv = sH[k*33 + tx];
            acc[0] = fmaf(a0.x, hv, acc[0]);
            acc[1] = fmaf(a0.y, hv, acc[1]);
            acc[2] = fmaf(a0.z, hv, acc[2]);
            acc[3] = fmaf(a0.w, hv, acc[3]);
            acc[4] = fmaf(a1.x, hv, acc[4]);
            acc[5] = fmaf(a1.y, hv, acc[5]);
            acc[6] = fmaf(a1.z, hv, acc[6]);
            acc[7] = fmaf(a1.w, hv, acc[7]);
        }
    }

    float lsum = 0.f, lss = 0.f;
#pragma unroll
    for (int i = 0; i < 8; i++) {
        int c = ty*8 + i;
        acc[i] += b2[c];
        lsum += acc[i];
        lss  += acc[i]*acc[i];
    }
    int g = ty >> 1;
    atomicAdd(&sacc[g], lsum);
    atomicAdd(&sss[g],  lss);
    __syncthreads();
    if (tid < 4) {
        atomicAdd(&G_S3[b*4 + tid],  (double)sacc[tid]);
        atomicAdd(&G_SS3[b*4 + tid], (double)sss[tid]);
        __threadfence();
    }
    __syncthreads();

    // grid-wide barrier (256 blocks all resident: 256 thr, ~26KB smem -> 8 CTAs/SM cap)
    if (tid == 0) {
        atomicAdd(&g_z.bar2, 1);
        while (atomicAdd(&g_z.bar2, 0) < 256) {}
    }
    __syncthreads();

    if (tid < 4) {
        double s  = atomicAdd(&G_S3[b*4 + tid],  0.0);
        double ss = atomicAdd(&G_SS3[b*4 + tid], 0.0);
        double mean = s * (1.0 / 65536.0);
        double var  = ss * (1.0 / 65536.0) - mean * mean;
        sMean[tid] = (float)mean;
        sRs[tid]   = (float)rsqrt(var + 1e-5);
    }
    __syncthreads();

#pragma unroll
    for (int i = 0; i < 8; i++) {
        int c = ty*8 + i;
        int gg = c >> 4;
        float ga = sRs[gg] * g2[c];
        float bo = be2[c] - sMean[gg] * ga;
        size_t off = (size_t)(b*CC + c)*NPTS + n0 + tx;
        out[off] = fmaf(acc[i], ga, bo) + x[off];
    }
}

extern "C" void kernel_launch(void* const* d_in, const int* in_sizes, int n_in,
                              void* d_out, int out_size) {
    const float* x   = (const float*)d_in[0];
    const float* pos = (const float*)d_in[1];
    const float* w1  = (const float*)d_in[2];
    const float* b1  = (const float*)d_in[3];
    const float* g1  = (const float*)d_in[4];
    const float* be1 = (const float*)d_in[5];
    const float* wd  = (const float*)d_in[6];
    const float* gd  = (const float*)d_in[7];
    const float* bed = (const float*)d_in[8];
    const float* w2  = (const float*)d_in[9];
    const float* b2  = (const float*)d_in[10];
    const float* g2  = (const float*)d_in[11];
    const float* be2 = (const float*)d_in[12];
    float* out = (float*)d_out;

    static int inited = 0;
    if (!inited) {
        cudaFuncSetAttribute(k_ball, cudaFuncAttributeMaxDynamicSharedMemorySize, 3*NPTS*4 + 32*NS*4);
        inited = 1;
    }

    void* p_z;
    cudaGetSymbolAddress(&p_z, g_z);
    cudaMemsetAsync(p_z, 0, sizeof(ZScratch));

    k_ball     <<<BB*NPTS/32, 1024, 3*NPTS*4 + 32*NS*4>>>(pos);
    k_gramstats<<<128, 256>>>(x, w1, b1);
    k_gemm1f   <<<dim3(NPTS/64, MM/64, BB), 256>>>(x, w1, b1, g1, be1, wd);
    k_gather   <<<BB*NPTS/8, 256>>>(wd, gd, bed);
    k_gemm2f   <<<dim3(NPTS/32, BB), 256>>>(w2, b2, x, g2, be2, out);
}